// round 8
// baseline (speedup 1.0000x reference)
#include <cuda_runtime.h>
#include <cuda_fp16.h>
#include <cstdint>

#define NE 8
#define NH 1024
#define NI 2048
#define NT 1024

// ---------------- device scratch (no allocations allowed) ----------------
__device__ int    g_counts[NE];
__device__ int    g_tok[NE * NT];
__device__ float  g_gate[NE * NT];
__device__ __half g_x16[(size_t)NT * NH];          // 2 MB
__device__ __half g_act[(size_t)NE * NT * NI];     // 33.5 MB

// ---------------- PTX helpers (base-PTX only: sm_100 safe) ----------------
__device__ __forceinline__ uint32_t smem_u32(const void* p) {
    uint32_t a;
    asm("{ .reg .u64 t; cvta.to.shared.u64 t, %1; cvt.u32.u64 %0, t; }" : "=r"(a) : "l"(p));
    return a;
}
__device__ __forceinline__ void ldm4(uint32_t* r, uint32_t addr) {
    asm volatile("ldmatrix.sync.aligned.m8n8.x4.shared.b16 {%0,%1,%2,%3}, [%4];"
                 : "=r"(r[0]), "=r"(r[1]), "=r"(r[2]), "=r"(r[3]) : "r"(addr));
}
__device__ __forceinline__ void mma16(float* c, const uint32_t* a, const uint32_t* b) {
    asm volatile(
        "mma.sync.aligned.m16n8k16.row.col.f32.f16.f16.f32 "
        "{%0,%1,%2,%3},{%4,%5,%6,%7},{%8,%9},{%0,%1,%2,%3};"
        : "+f"(c[0]), "+f"(c[1]), "+f"(c[2]), "+f"(c[3])
        : "r"(a[0]), "r"(a[1]), "r"(a[2]), "r"(a[3]), "r"(b[0]), "r"(b[1]));
}
__device__ __forceinline__ void cpa16(uint32_t dst, const void* src) {
    asm volatile("cp.async.cg.shared.global [%0], [%1], 16;" :: "r"(dst), "l"(src));
}
__device__ __forceinline__ void cp_commit() { asm volatile("cp.async.commit_group;"); }
template <int N> __device__ __forceinline__ void cp_wait() {
    asm volatile("cp.async.wait_group %0;" :: "n"(N));
}
__device__ __forceinline__ uint32_t pkh2(float a, float b) {
    __half2 t = __floats2half2_rn(a, b);
    return *reinterpret_cast<uint32_t*>(&t);
}

// smem geometry: A tile 128 rows x 64 fp16 (128B, stride 144); B tile 64 rows.
#define RSTRIDE 144
#define A_TILE (128 * RSTRIDE)                     // 18432
#define B_TILE (64 * RSTRIDE)                      // 9216
#define OFF_A(i) (1024 + (i) * A_TILE)             // i in 0..1
#define OFF_B(j) (1024 + 2 * A_TILE + (j) * B_TILE)// j in 0..1
#define SMEM_TOT (1024 + 2 * A_TILE + 2 * B_TILE)  // 56320 -> 3 CTAs/SM

// ---------------- kernel 0: zero out + counts, x -> fp16 ----------------
__global__ void prep_kernel(const float* __restrict__ x, float* __restrict__ out) {
    int i = blockIdx.x * 256 + threadIdx.x;
    if (i < NT * NH) { out[i] = 0.f; g_x16[i] = __float2half_rn(x[i]); }
    if (i < NE) g_counts[i] = 0;
}

// ---------------- kernel 1: router ----------------
__global__ void router_kernel(const float* __restrict__ logits) {
    int t = blockIdx.x * 256 + threadIdx.x;
    if (t >= NT) return;
    float b0 = -1e30f, b1 = -1e30f;
    int i0 = 0, i1 = 0;
#pragma unroll
    for (int ei = 0; ei < NE; ++ei) {
        float l = logits[t * NE + ei];
        if (l > b0) { b1 = b0; i1 = i0; b0 = l; i0 = ei; }
        else if (l > b1) { b1 = l; i1 = ei; }
    }
    float w0 = 1.f / (1.f + expf(b1 - b0));
    float w1 = 1.f - w0;
    int s0 = atomicAdd(&g_counts[i0], 1);
    g_tok[i0 * NT + s0] = t;  g_gate[i0 * NT + s0] = w0;
    int s1 = atomicAdd(&g_counts[i1], 1);
    g_tok[i1 * NT + s1] = t;  g_gate[i1 * NT + s1] = w1;
}

// ---------------- GEMM1: 128 tokens x 32 inter cols (glu+lin), SwiGLU fused ----------------
// B tile = 64 rows: [0,32) glu rows, [32,64) lin rows. Warp: 32m x 16n, both halves.
__global__ __launch_bounds__(256, 3)
void gemm1_k(const float* __restrict__ w13, const float* __restrict__ b13) {
    const int e   = blockIdx.z;
    const int cnt = g_counts[e];
    const int m0  = blockIdx.y * 128;
    if (m0 >= cnt) return;
    const int n0g = blockIdx.x * 32;
    const int S   = 16;

    extern __shared__ char sm[];
    const uint32_t smb = smem_u32(sm);
    const int tid = threadIdx.x, wid = tid >> 5, lane = tid & 31;
    const int lr = lane >> 2, lc = lane & 3;
    const int wm = (wid & 3) * 32, wng = (wid >> 2) * 16;
    int* sTok = (int*)sm;

    if (tid < 128) { int s = m0 + tid; sTok[tid] = (s < cnt) ? g_tok[e * NT + s] : 0; }
    __syncthreads();

    // acc[half][mt][nt][4]: 2*2*2*4 = 32 regs
    float acc[2][2][2][4];
#pragma unroll
    for (int h = 0; h < 2; ++h)
#pragma unroll
        for (int mt = 0; mt < 2; ++mt)
#pragma unroll
            for (int nt = 0; nt < 2; ++nt)
#pragma unroll
                for (int i = 0; i < 4; ++i) acc[h][mt][nt][i] = 0.f;

    const int ar = tid >> 3,  ac = tid & 7;      // A: rows ar+32i, 16B chunk ac
    const int br = tid >> 2,  bq = tid & 3;      // B: row br, float4 chunks bq+4i
    const int bgrow = (br < 32) ? (n0g + br) : (2048 + n0g + (br - 32));
    const float* brow = w13 + ((size_t)e * 4096 + bgrow) * NH;

    const uint32_t aoff = (uint32_t)((wm + (lane & 15)) * RSTRIDE + (lane >> 4) * 16);
    const uint32_t boff = (uint32_t)(((lane & 7) + ((lane >> 4) << 3)) * RSTRIDE
                                     + ((lane >> 3) & 1) * 16);

    const __half* arow0 = g_x16 + (size_t)sTok[ar] * NH;
    const __half* arow1 = g_x16 + (size_t)sTok[ar + 32] * NH;
    const __half* arow2 = g_x16 + (size_t)sTok[ar + 64] * NH;
    const __half* arow3 = g_x16 + (size_t)sTok[ar + 96] * NH;

    float4 b4[4];
    // ---- prologue: A(0) cp.async; B(0) LDG->STS; B(1) LDG
    cpa16(smb + OFF_A(0) + (ar)      * RSTRIDE + ac * 16, arow0 + ac * 8);
    cpa16(smb + OFF_A(0) + (ar + 32) * RSTRIDE + ac * 16, arow1 + ac * 8);
    cpa16(smb + OFF_A(0) + (ar + 64) * RSTRIDE + ac * 16, arow2 + ac * 8);
    cpa16(smb + OFF_A(0) + (ar + 96) * RSTRIDE + ac * 16, arow3 + ac * 8);
    cp_commit();
#pragma unroll
    for (int i = 0; i < 4; ++i) b4[i] = *(const float4*)(brow + (bq + 4 * i) * 4);
#pragma unroll
    for (int i = 0; i < 4; ++i) {
        uint2 p = make_uint2(pkh2(b4[i].x, b4[i].y), pkh2(b4[i].z, b4[i].w));
        *(uint2*)(sm + OFF_B(0) + br * RSTRIDE + (bq + 4 * i) * 8) = p;
    }
#pragma unroll
    for (int i = 0; i < 4; ++i) b4[i] = *(const float4*)(brow + 64 + (bq + 4 * i) * 4);
    cp_wait<0>();
    __syncthreads();

#pragma unroll 1
    for (int s = 0; s < S; ++s) {
        const int cur = s & 1;
        const uint32_t stA = OFF_A(cur), stB = OFF_B(cur);
        if (s + 1 < S) {
            const int k0n = (s + 1) * 64;
            const uint32_t dst = smb + OFF_A(cur ^ 1);
            cpa16(dst + (ar)      * RSTRIDE + ac * 16, arow0 + k0n + ac * 8);
            cpa16(dst + (ar + 32) * RSTRIDE + ac * 16, arow1 + k0n + ac * 8);
            cpa16(dst + (ar + 64) * RSTRIDE + ac * 16, arow2 + k0n + ac * 8);
            cpa16(dst + (ar + 96) * RSTRIDE + ac * 16, arow3 + k0n + ac * 8);
            cp_commit();
#pragma unroll
            for (int i = 0; i < 4; ++i) {
                uint2 p = make_uint2(pkh2(b4[i].x, b4[i].y), pkh2(b4[i].z, b4[i].w));
                *(uint2*)(sm + OFF_B(cur ^ 1) + br * RSTRIDE + (bq + 4 * i) * 8) = p;
            }
        }
        if (s + 2 < S) {
            const int k0n2 = (s + 2) * 64;
#pragma unroll
            for (int i = 0; i < 4; ++i)
                b4[i] = *(const float4*)(brow + k0n2 + (bq + 4 * i) * 4);
        }
#pragma unroll
        for (int k16 = 0; k16 < 4; ++k16) {
            uint32_t a[2][4];
            uint32_t abase = smb + stA + aoff + k16 * 32;
            ldm4(a[0], abase);
            ldm4(a[1], abase + 16 * RSTRIDE);
            uint32_t bg[4], bl[4];
            ldm4(bg, smb + stB + boff + wng * RSTRIDE + k16 * 32);
            ldm4(bl, smb + stB + boff + (32 + wng) * RSTRIDE + k16 * 32);
            mma16(acc[0][0][0], a[0], bg);
            mma16(acc[0][1][0], a[1], bg);
            mma16(acc[0][0][1], a[0], bg + 2);
            mma16(acc[0][1][1], a[1], bg + 2);
            mma16(acc[1][0][0], a[0], bl);
            mma16(acc[1][1][0], a[1], bl);
            mma16(acc[1][0][1], a[0], bl + 2);
            mma16(acc[1][1][1], a[1], bl + 2);
        }
        if (s + 1 < S) cp_wait<0>();
        __syncthreads();
    }

    // ---- epilogue: SwiGLU in regs, stage 128x32 fp16 tile (stride 80), store
    const float* bgp = b13 + (size_t)e * 4096 + n0g;
    const float* blp = b13 + (size_t)e * 4096 + 2048 + n0g;
#pragma unroll
    for (int mt = 0; mt < 2; ++mt)
#pragma unroll
        for (int nt = 0; nt < 2; ++nt)
#pragma unroll
            for (int i = 0; i < 2; ++i) {
                int row = wm + mt * 16 + lr + i * 8;
                int col = wng + nt * 8 + lc * 2;
                float g0 = acc[0][mt][nt][i * 2 + 0] + bgp[col];
                float g1 = acc[0][mt][nt][i * 2 + 1] + bgp[col + 1];
                float l0 = acc[1][mt][nt][i * 2 + 0] + blp[col];
                float l1 = acc[1][mt][nt][i * 2 + 1] + blp[col + 1];
                float a0 = g0 * (1.f / (1.f + __expf(-1.702f * g0))) * (l0 + 1.0f);
                float a1 = g1 * (1.f / (1.f + __expf(-1.702f * g1))) * (l1 + 1.0f);
                *(uint32_t*)(sm + 1024 + row * 80 + col * 2) = pkh2(a0, a1);
            }
    __syncthreads();
    // FIX (R7 bug): 128 rows x 4 chunks of 16B = 512 writes; cover ALL 4 chunks.
#pragma unroll
    for (int it = 0; it < 2; ++it) {
        int idx = it * 256 + tid;          // 0..511
        int r = idx >> 2, c = idx & 3;     // row 0..127, chunk 0..3
        int slot = m0 + r;
        if (slot < cnt) {
            uint4 v = *(uint4*)(sm + 1024 + r * 80 + c * 16);
            *(uint4*)(g_act + ((size_t)e * NT + slot) * NI + n0g + c * 8) = v;
        }
    }
}

// ---------------- GEMM2: 128 slots x 64 out cols, gated atomic scatter ----------------
__global__ __launch_bounds__(256, 3)
void gemm2_k(const float* __restrict__ w2, const float* __restrict__ b2,
             float* __restrict__ out) {
    const int e   = blockIdx.z;
    const int cnt = g_counts[e];
    const int m0  = blockIdx.y * 128;
    if (m0 >= cnt) return;
    const int n0  = blockIdx.x * 64;
    const int S   = 32;

    extern __shared__ char sm[];
    const uint32_t smb = smem_u32(sm);
    const int tid = threadIdx.x, wid = tid >> 5, lane = tid & 31;
    const int lr = lane >> 2, lc = lane & 3;
    const int wm = (wid & 3) * 32, wn = (wid >> 2) * 32;
    int*   sTok = (int*)sm;
    float* sG   = (float*)(sm + 512);

    if (tid < 128) {
        int slot = m0 + tid;
        sTok[tid] = (slot < cnt) ? g_tok[e * NT + slot] : 0;
        sG[tid]   = (slot < cnt) ? g_gate[e * NT + slot] : 0.f;
    }
    __syncthreads();

    float acc[2][4][4];   // 32 regs
#pragma unroll
    for (int mt = 0; mt < 2; ++mt)
#pragma unroll
        for (int nt = 0; nt < 4; ++nt)
#pragma unroll
            for (int i = 0; i < 4; ++i) acc[mt][nt][i] = 0.f;

    const int ar = tid >> 3,  ac = tid & 7;
    const int br = tid >> 2,  bq = tid & 3;
    const float* brow = w2 + ((size_t)e * NH + n0 + br) * NI;
    const __half* abase = g_act + ((size_t)e * NT + m0 + ar) * NI;

    const uint32_t aoff = (uint32_t)((wm + (lane & 15)) * RSTRIDE + (lane >> 4) * 16);
    const uint32_t boff = (uint32_t)(((lane & 7) + ((lane >> 4) << 3)) * RSTRIDE
                                     + ((lane >> 3) & 1) * 16);

    float4 b4[4];
    // ---- prologue
#pragma unroll
    for (int i = 0; i < 4; ++i)
        cpa16(smb + OFF_A(0) + (ar + i * 32) * RSTRIDE + ac * 16,
              abase + (size_t)i * 32 * NI + ac * 8);
    cp_commit();
#pragma unroll
    for (int i = 0; i < 4; ++i) b4[i] = *(const float4*)(brow + (bq + 4 * i) * 4);
#pragma unroll
    for (int i = 0; i < 4; ++i) {
        uint2 p = make_uint2(pkh2(b4[i].x, b4[i].y), pkh2(b4[i].z, b4[i].w));
        *(uint2*)(sm + OFF_B(0) + br * RSTRIDE + (bq + 4 * i) * 8) = p;
    }
#pragma unroll
    for (int i = 0; i < 4; ++i) b4[i] = *(const float4*)(brow + 64 + (bq + 4 * i) * 4);
    cp_wait<0>();
    __syncthreads();

#pragma unroll 1
    for (int s = 0; s < S; ++s) {
        const int cur = s & 1;
        const uint32_t stA = OFF_A(cur), stB = OFF_B(cur);
        if (s + 1 < S) {
            const int k0n = (s + 1) * 64;
            const uint32_t dst = smb + OFF_A(cur ^ 1);
#pragma unroll
            for (int i = 0; i < 4; ++i)
                cpa16(dst + (ar + i * 32) * RSTRIDE + ac * 16,
                      abase + (size_t)i * 32 * NI + k0n + ac * 8);
            cp_commit();
#pragma unroll
            for (int i = 0; i < 4; ++i) {
                uint2 p = make_uint2(pkh2(b4[i].x, b4[i].y), pkh2(b4[i].z, b4[i].w));
                *(uint2*)(sm + OFF_B(cur ^ 1) + br * RSTRIDE + (bq + 4 * i) * 8) = p;
            }
        }
        if (s + 2 < S) {
            const int k0n2 = (s + 2) * 64;
#pragma unroll
            for (int i = 0; i < 4; ++i)
                b4[i] = *(const float4*)(brow + k0n2 + (bq + 4 * i) * 4);
        }
#pragma unroll
        for (int k16 = 0; k16 < 4; ++k16) {
            uint32_t a[2][4];
            uint32_t abase2 = smb + stA + aoff + k16 * 32;
            ldm4(a[0], abase2);
            ldm4(a[1], abase2 + 16 * RSTRIDE);
#pragma unroll
            for (int ntp = 0; ntp < 2; ++ntp) {
                uint32_t b[4];
                ldm4(b, smb + stB + boff + (wn + ntp * 16) * RSTRIDE + k16 * 32);
                mma16(acc[0][ntp * 2],     a[0], b);
                mma16(acc[1][ntp * 2],     a[1], b);
                mma16(acc[0][ntp * 2 + 1], a[0], b + 2);
                mma16(acc[1][ntp * 2 + 1], a[1], b + 2);
            }
        }
        if (s + 1 < S) cp_wait<0>();
        __syncthreads();
    }

    // epilogue: out[tok, n0+col] += gate * (acc + b2)
    const float* bb = b2 + (size_t)e * NH + n0;
#pragma unroll
    for (int mt = 0; mt < 2; ++mt)
#pragma unroll
        for (int i = 0; i < 2; ++i) {
            int row = wm + mt * 16 + lr + i * 8;
            int slot = m0 + row;
            if (slot >= cnt) continue;
            int tok = sTok[row];
            float gate = sG[row];
            float* orow = out + (size_t)tok * NH + n0;
#pragma unroll
            for (int nt = 0; nt < 4; ++nt) {
                int col = wn + nt * 8 + lc * 2;
                atomicAdd(orow + col,     gate * (acc[mt][nt][i * 2 + 0] + bb[col]));
                atomicAdd(orow + col + 1, gate * (acc[mt][nt][i * 2 + 1] + bb[col + 1]));
            }
        }
}

// ---------------- host entry ----------------
extern "C" void kernel_launch(void* const* d_in, const int* in_sizes, int n_in,
                              void* d_out, int out_size) {
    const float* x      = (const float*)d_in[0];
    const float* logits = (const float*)d_in[1];
    const float* w13    = (const float*)d_in[2];
    const float* w2     = (const float*)d_in[3];
    const float* b13    = (const float*)d_in[4];
    const float* b2     = (const float*)d_in[5];
    float* out          = (float*)d_out;

    cudaFuncSetAttribute(gemm1_k, cudaFuncAttributeMaxDynamicSharedMemorySize, SMEM_TOT);
    cudaFuncSetAttribute(gemm2_k, cudaFuncAttributeMaxDynamicSharedMemorySize, SMEM_TOT);

    prep_kernel<<<(NT * NH + 255) / 256, 256>>>(x, out);
    router_kernel<<<(NT + 255) / 256, 256>>>(logits);
    gemm1_k<<<dim3(NI / 32, NT / 128, NE), 256, SMEM_TOT>>>(w13, b13);
    gemm2_k<<<dim3(NH / 64, NT / 128, NE), 256, SMEM_TOT>>>(w2, b2, out);
}

// round 9
// speedup vs baseline: 1.2621x; 1.2621x over previous
#include <cuda_runtime.h>
#include <cuda_fp16.h>
#include <cstdint>

#define NE 8
#define NH 1024
#define NI 2048
#define NT 1024

// ---------------- device scratch (no allocations allowed) ----------------
__device__ int    g_counts[NE];
__device__ int    g_tok[NE * NT];
__device__ float  g_gate[NE * NT];
__device__ __half g_x16[(size_t)NT * NH];          // 2 MB
__device__ __half g_act[(size_t)NE * NT * NI];     // 33.5 MB

// ---------------- PTX helpers (base-PTX only: sm_100 safe) ----------------
__device__ __forceinline__ uint32_t smem_u32(const void* p) {
    uint32_t a;
    asm("{ .reg .u64 t; cvta.to.shared.u64 t, %1; cvt.u32.u64 %0, t; }" : "=r"(a) : "l"(p));
    return a;
}
__device__ __forceinline__ void ldm4(uint32_t* r, uint32_t addr) {
    asm volatile("ldmatrix.sync.aligned.m8n8.x4.shared.b16 {%0,%1,%2,%3}, [%4];"
                 : "=r"(r[0]), "=r"(r[1]), "=r"(r[2]), "=r"(r[3]) : "r"(addr));
}
__device__ __forceinline__ void mma16(float* c, const uint32_t* a, const uint32_t* b) {
    asm volatile(
        "mma.sync.aligned.m16n8k16.row.col.f32.f16.f16.f32 "
        "{%0,%1,%2,%3},{%4,%5,%6,%7},{%8,%9},{%0,%1,%2,%3};"
        : "+f"(c[0]), "+f"(c[1]), "+f"(c[2]), "+f"(c[3])
        : "r"(a[0]), "r"(a[1]), "r"(a[2]), "r"(a[3]), "r"(b[0]), "r"(b[1]));
}
__device__ __forceinline__ void cpa16(uint32_t dst, const void* src) {
    asm volatile("cp.async.cg.shared.global [%0], [%1], 16;" :: "r"(dst), "l"(src));
}
__device__ __forceinline__ void cp_commit() { asm volatile("cp.async.commit_group;"); }
template <int N> __device__ __forceinline__ void cp_wait() {
    asm volatile("cp.async.wait_group %0;" :: "n"(N));
}
__device__ __forceinline__ uint32_t pkh2(float a, float b) {
    __half2 t = __floats2half2_rn(a, b);
    return *reinterpret_cast<uint32_t*>(&t);
}

#define RSTRIDE 144
// gemm1 smem: A 128 rows, B 128 rows (glu64+lin64), 2 buffers each
#define TILE_B  (128 * RSTRIDE)                    // 18432
#define OFF_A(b) (1024 + (b) * 2 * TILE_B)
#define OFF_B(b) (1024 + (b) * 2 * TILE_B + TILE_B)
#define SMEM_G1 (1024 + 4 * TILE_B)                // 74752
// gemm2 smem: A 128 rows, B 64 rows, 2 buffers each
#define B2_TILE (64 * RSTRIDE)                     // 9216
#define OFF2_A(i) (1024 + (i) * TILE_B)
#define OFF2_B(j) (1024 + 2 * TILE_B + (j) * B2_TILE)
#define SMEM_G2 (1024 + 2 * TILE_B + 2 * B2_TILE)  // 56320 -> 4 CTAs/SM @128thr

// ---------------- kernel 0: zero out + counts, x -> fp16 ----------------
__global__ void prep_kernel(const float* __restrict__ x, float* __restrict__ out) {
    int i = blockIdx.x * 256 + threadIdx.x;
    if (i < NT * NH) { out[i] = 0.f; g_x16[i] = __float2half_rn(x[i]); }
    if (i < NE) g_counts[i] = 0;
}

// ---------------- kernel 1: router ----------------
__global__ void router_kernel(const float* __restrict__ logits) {
    int t = blockIdx.x * 256 + threadIdx.x;
    if (t >= NT) return;
    float b0 = -1e30f, b1 = -1e30f;
    int i0 = 0, i1 = 0;
#pragma unroll
    for (int ei = 0; ei < NE; ++ei) {
        float l = logits[t * NE + ei];
        if (l > b0) { b1 = b0; i1 = i0; b0 = l; i0 = ei; }
        else if (l > b1) { b1 = l; i1 = ei; }
    }
    float w0 = 1.f / (1.f + expf(b1 - b0));
    float w1 = 1.f - w0;
    int s0 = atomicAdd(&g_counts[i0], 1);
    g_tok[i0 * NT + s0] = t;  g_gate[i0 * NT + s0] = w0;
    int s1 = atomicAdd(&g_counts[i1], 1);
    g_tok[i1 * NT + s1] = t;  g_gate[i1 * NT + s1] = w1;
}

// ---------------- GEMM1 (R4 verbatim, grid x=m / y=n): 128 tok x 64 inter ----------------
__global__ __launch_bounds__(256, 2)
void gemm1_k(const float* __restrict__ w13, const float* __restrict__ b13) {
    const int e   = blockIdx.z;
    const int cnt = g_counts[e];
    const int m0  = blockIdx.x * 128;
    if (m0 >= cnt) return;
    const int n0i = blockIdx.y * 64;
    const int S   = 16;

    extern __shared__ char sm[];
    const uint32_t smb = smem_u32(sm);
    const int tid = threadIdx.x, wid = tid >> 5, lane = tid & 31;
    const int lr = lane >> 2, lc = lane & 3;
    const int wm = (wid & 3) * 32, wn = (wid >> 2) * 32;
    int* sTok = (int*)sm;

    if (tid < 128) { int s = m0 + tid; sTok[tid] = (s < cnt) ? g_tok[e * NT + s] : 0; }
    __syncthreads();

    float acc[2][8][4];
#pragma unroll
    for (int mt = 0; mt < 2; ++mt)
#pragma unroll
        for (int nt = 0; nt < 8; ++nt)
#pragma unroll
            for (int i = 0; i < 4; ++i) acc[mt][nt][i] = 0.f;

    const int ar = tid >> 3,  ac = tid & 7;
    const int br = tid >> 4,  bc = tid & 15;
    const uint32_t aoff = (uint32_t)((wm + (lane & 15)) * RSTRIDE + (lane >> 4) * 16);
    const uint32_t boff = (uint32_t)(((lane & 7) + ((lane >> 4) << 3)) * RSTRIDE
                                     + ((lane >> 3) & 1) * 16);

    const __half* arow0 = g_x16 + (size_t)sTok[ar] * NH;
    const __half* arow1 = g_x16 + (size_t)sTok[ar + 32] * NH;
    const __half* arow2 = g_x16 + (size_t)sTok[ar + 64] * NH;
    const __half* arow3 = g_x16 + (size_t)sTok[ar + 96] * NH;

    float4 b4[8];
    // prologue: A(0) cp.async; B(0) LDG->STS; B(1) LDG
    cpa16(smb + OFF_A(0) + (ar)      * RSTRIDE + ac * 16, arow0 + ac * 8);
    cpa16(smb + OFF_A(0) + (ar + 32) * RSTRIDE + ac * 16, arow1 + ac * 8);
    cpa16(smb + OFF_A(0) + (ar + 64) * RSTRIDE + ac * 16, arow2 + ac * 8);
    cpa16(smb + OFF_A(0) + (ar + 96) * RSTRIDE + ac * 16, arow3 + ac * 8);
    cp_commit();
#pragma unroll
    for (int i = 0; i < 8; ++i) {
        int r = br + i * 16;
        int grow = (r < 64) ? (n0i + r) : (2048 + n0i + r - 64);
        b4[i] = *(const float4*)(w13 + ((size_t)e * 4096 + grow) * NH + bc * 4);
    }
#pragma unroll
    for (int i = 0; i < 8; ++i) {
        int r = br + i * 16;
        uint2 p = make_uint2(pkh2(b4[i].x, b4[i].y), pkh2(b4[i].z, b4[i].w));
        *(uint2*)(sm + OFF_B(0) + r * RSTRIDE + bc * 8) = p;
    }
#pragma unroll
    for (int i = 0; i < 8; ++i) {
        int r = br + i * 16;
        int grow = (r < 64) ? (n0i + r) : (2048 + n0i + r - 64);
        b4[i] = *(const float4*)(w13 + ((size_t)e * 4096 + grow) * NH + 64 + bc * 4);
    }
    cp_wait<0>();
    __syncthreads();

#pragma unroll 1
    for (int s = 0; s < S; ++s) {
        const int cur = s & 1;
        const uint32_t stA = OFF_A(cur), stB = OFF_B(cur);
        if (s + 1 < S) {
            const int k0n = (s + 1) * 64;
            const uint32_t dst = smb + OFF_A(cur ^ 1);
            cpa16(dst + (ar)      * RSTRIDE + ac * 16, arow0 + k0n + ac * 8);
            cpa16(dst + (ar + 32) * RSTRIDE + ac * 16, arow1 + k0n + ac * 8);
            cpa16(dst + (ar + 64) * RSTRIDE + ac * 16, arow2 + k0n + ac * 8);
            cpa16(dst + (ar + 96) * RSTRIDE + ac * 16, arow3 + k0n + ac * 8);
            cp_commit();
#pragma unroll
            for (int i = 0; i < 8; ++i) {
                int r = br + i * 16;
                uint2 p = make_uint2(pkh2(b4[i].x, b4[i].y), pkh2(b4[i].z, b4[i].w));
                *(uint2*)(sm + OFF_B(cur ^ 1) + r * RSTRIDE + bc * 8) = p;
            }
        }
        if (s + 2 < S) {
            const int k0n2 = (s + 2) * 64;
#pragma unroll
            for (int i = 0; i < 8; ++i) {
                int r = br + i * 16;
                int grow = (r < 64) ? (n0i + r) : (2048 + n0i + r - 64);
                b4[i] = *(const float4*)(w13 + ((size_t)e * 4096 + grow) * NH + k0n2 + bc * 4);
            }
        }
#pragma unroll
        for (int k16 = 0; k16 < 4; ++k16) {
            uint32_t a[2][4];
            uint32_t abase = smb + stA + aoff + k16 * 32;
            ldm4(a[0], abase);
            ldm4(a[1], abase + 16 * RSTRIDE);
#pragma unroll
            for (int ntp = 0; ntp < 4; ++ntp) {
                int browoff = ((ntp >= 2) ? 64 : 0) + wn + ((ntp & 1) << 4);
                uint32_t b[4];
                ldm4(b, smb + stB + boff + browoff * RSTRIDE + k16 * 32);
                mma16(acc[0][ntp * 2],     a[0], b);
                mma16(acc[1][ntp * 2],     a[1], b);
                mma16(acc[0][ntp * 2 + 1], a[0], b + 2);
                mma16(acc[1][ntp * 2 + 1], a[1], b + 2);
            }
        }
        if (s + 1 < S) cp_wait<0>();
        __syncthreads();
    }

    // epilogue: SwiGLU in regs, stage act tile, coalesced store
    const float* bg = b13 + (size_t)e * 4096 + n0i;
    const float* bl = b13 + (size_t)e * 4096 + 2048 + n0i;
#pragma unroll
    for (int mt = 0; mt < 2; ++mt)
#pragma unroll
        for (int nt = 0; nt < 4; ++nt)
#pragma unroll
            for (int i = 0; i < 2; ++i) {
                int row = wm + mt * 16 + lr + i * 8;
                int col = wn + nt * 8 + lc * 2;
                float g0 = acc[0][nt * 1 + 0 + (nt)][0];  // placeholder (overwritten below)
                (void)g0;
                float gg0 = acc[0][nt][i * 2 + 0];
                (void)gg0;
                float x0 = acc[mt][nt][i * 2 + 0] + bg[col];
                float x1 = acc[mt][nt][i * 2 + 1] + bg[col + 1];
                float l0 = acc[mt][nt + 4][i * 2 + 0] + bl[col];
                float l1 = acc[mt][nt + 4][i * 2 + 1] + bl[col + 1];
                float a0 = x0 * (1.f / (1.f + __expf(-1.702f * x0))) * (l0 + 1.0f);
                float a1 = x1 * (1.f / (1.f + __expf(-1.702f * x1))) * (l1 + 1.0f);
                *(uint32_t*)(sm + 1024 + row * RSTRIDE + col * 2) = pkh2(a0, a1);
            }
    __syncthreads();
#pragma unroll
    for (int i = 0; i < 4; ++i) {
        int idx = i * 256 + tid;
        int r = idx >> 3, c = idx & 7;
        int slot = m0 + r;
        if (slot < cnt) {
            uint4 v = *(uint4*)(sm + 1024 + r * RSTRIDE + c * 16);
            *(uint4*)(g_act + ((size_t)e * NT + slot) * NI + n0i + c * 8) = v;
        }
    }
}

// ---------------- GEMM2: 128-thread CTA, BM=128 x BN=64, warp=32m x 64n ----------------
__global__ __launch_bounds__(128, 4)
void gemm2_k(const float* __restrict__ w2, const float* __restrict__ b2,
             float* __restrict__ out) {
    const int e   = blockIdx.z;
    const int cnt = g_counts[e];
    const int m0  = blockIdx.x * 128;
    if (m0 >= cnt) return;
    const int n0  = blockIdx.y * 64;
    const int S   = 32;

    extern __shared__ char sm[];
    const uint32_t smb = smem_u32(sm);
    const int tid = threadIdx.x, wid = tid >> 5, lane = tid & 31;
    const int lr = lane >> 2, lc = lane & 3;
    const int wm = wid * 32;
    int*   sTok = (int*)sm;
    float* sG   = (float*)(sm + 512);

    { int slot = m0 + tid;
      sTok[tid] = (slot < cnt) ? g_tok[e * NT + slot] : 0;
      sG[tid]   = (slot < cnt) ? g_gate[e * NT + slot] : 0.f; }
    __syncthreads();

    float acc[2][8][4];   // 64 regs: mt(2, rows +0/+16) x nt(8, 8-col groups) x 4
#pragma unroll
    for (int mt = 0; mt < 2; ++mt)
#pragma unroll
        for (int nt = 0; nt < 8; ++nt)
#pragma unroll
            for (int i = 0; i < 4; ++i) acc[mt][nt][i] = 0.f;

    const int ar = tid >> 3,  ac = tid & 7;     // A: rows ar+16i (8 iters)
    const int br = tid >> 4,  bc = tid & 15;    // B: rows br+8i  (8 iters)
    const uint32_t aoff = (uint32_t)((wm + (lane & 15)) * RSTRIDE + (lane >> 4) * 16);
    const uint32_t boff = (uint32_t)(((lane & 7) + ((lane >> 4) << 3)) * RSTRIDE
                                     + ((lane >> 3) & 1) * 16);

    const __half* abase = g_act + ((size_t)e * NT + m0) * NI;

    float4 b4[8];
    // prologue: A(0) cp.async; B(0) LDG->STS; B(1) LDG
#pragma unroll
    for (int i = 0; i < 8; ++i) {
        int r = ar + i * 16;
        cpa16(smb + OFF2_A(0) + r * RSTRIDE + ac * 16, abase + (size_t)r * NI + ac * 8);
    }
    cp_commit();
#pragma unroll
    for (int i = 0; i < 8; ++i)
        b4[i] = *(const float4*)(w2 + ((size_t)e * NH + n0 + br + i * 8) * NI + bc * 4);
#pragma unroll
    for (int i = 0; i < 8; ++i) {
        uint2 p = make_uint2(pkh2(b4[i].x, b4[i].y), pkh2(b4[i].z, b4[i].w));
        *(uint2*)(sm + OFF2_B(0) + (br + i * 8) * RSTRIDE + bc * 8) = p;
    }
#pragma unroll
    for (int i = 0; i < 8; ++i)
        b4[i] = *(const float4*)(w2 + ((size_t)e * NH + n0 + br + i * 8) * NI + 64 + bc * 4);
    cp_wait<0>();
    __syncthreads();

#pragma unroll 1
    for (int s = 0; s < S; ++s) {
        const int cur = s & 1;
        const uint32_t stA = OFF2_A(cur), stB = OFF2_B(cur);
        if (s + 1 < S) {
            const int k0n = (s + 1) * 64;
            const uint32_t dst = smb + OFF2_A(cur ^ 1);
#pragma unroll
            for (int i = 0; i < 8; ++i) {
                int r = ar + i * 16;
                cpa16(dst + r * RSTRIDE + ac * 16, abase + (size_t)r * NI + k0n + ac * 8);
            }
            cp_commit();
#pragma unroll
            for (int i = 0; i < 8; ++i) {
                uint2 p = make_uint2(pkh2(b4[i].x, b4[i].y), pkh2(b4[i].z, b4[i].w));
                *(uint2*)(sm + OFF2_B(cur ^ 1) + (br + i * 8) * RSTRIDE + bc * 8) = p;
            }
        }
        if (s + 2 < S) {
            const int k0n2 = (s + 2) * 64;
#pragma unroll
            for (int i = 0; i < 8; ++i)
                b4[i] = *(const float4*)(w2 + ((size_t)e * NH + n0 + br + i * 8) * NI + k0n2 + bc * 4);
        }
#pragma unroll
        for (int k16 = 0; k16 < 4; ++k16) {
            uint32_t a[2][4];
            uint32_t ab = smb + stA + aoff + k16 * 32;
            ldm4(a[0], ab);
            ldm4(a[1], ab + 16 * RSTRIDE);
#pragma unroll
            for (int ntp = 0; ntp < 4; ++ntp) {
                uint32_t b[4];
                ldm4(b, smb + stB + boff + ntp * 16 * RSTRIDE + k16 * 32);
                mma16(acc[0][ntp * 2],     a[0], b);
                mma16(acc[1][ntp * 2],     a[1], b);
                mma16(acc[0][ntp * 2 + 1], a[0], b + 2);
                mma16(acc[1][ntp * 2 + 1], a[1], b + 2);
            }
        }
        if (s + 1 < S) cp_wait<0>();
        __syncthreads();
    }

    // epilogue: out[tok, n0+col] += gate * (acc + b2)
    const float* bb = b2 + (size_t)e * NH + n0;
#pragma unroll
    for (int mt = 0; mt < 2; ++mt)
#pragma unroll
        for (int i = 0; i < 2; ++i) {
            int row = wm + mt * 16 + lr + i * 8;
            int slot = m0 + row;
            if (slot >= cnt) continue;
            int tok = sTok[row];
            float gate = sG[row];
            float* orow = out + (size_t)tok * NH + n0;
#pragma unroll
            for (int nt = 0; nt < 8; ++nt) {
                int col = nt * 8 + lc * 2;
                atomicAdd(orow + col,     gate * (acc[mt][nt][i * 2 + 0] + bb[col]));
                atomicAdd(orow + col + 1, gate * (acc[mt][nt][i * 2 + 1] + bb[col + 1]));
            }
        }
}

// ---------------- host entry ----------------
extern "C" void kernel_launch(void* const* d_in, const int* in_sizes, int n_in,
                              void* d_out, int out_size) {
    const float* x      = (const float*)d_in[0];
    const float* logits = (const float*)d_in[1];
    const float* w13    = (const float*)d_in[2];
    const float* w2     = (const float*)d_in[3];
    const float* b13    = (const float*)d_in[4];
    const float* b2     = (const float*)d_in[5];
    float* out          = (float*)d_out;

    cudaFuncSetAttribute(gemm1_k, cudaFuncAttributeMaxDynamicSharedMemorySize, SMEM_G1);
    cudaFuncSetAttribute(gemm2_k, cudaFuncAttributeMaxDynamicSharedMemorySize, SMEM_G2);

    prep_kernel<<<(NT * NH + 255) / 256, 256>>>(x, out);
    router_kernel<<<(NT + 255) / 256, 256>>>(logits);
    gemm1_k<<<dim3(NT / 128, NI / 64, NE), 256, SMEM_G1>>>(w13, b13);
    gemm2_k<<<dim3(NT / 128, NH / 64, NE), 128, SMEM_G2>>>(w2, b2, out);
}

// round 10
// speedup vs baseline: 1.3254x; 1.0502x over previous
#include <cuda_runtime.h>
#include <cuda_fp16.h>
#include <cstdint>

#define NE 8
#define NH 1024
#define NI 2048
#define NT 1024

// ---------------- device scratch (no allocations allowed) ----------------
__device__ int    g_counts[NE];
__device__ int    g_tok[NE * NT];
__device__ float  g_gate[NE * NT];
__device__ __half g_x16[(size_t)NT * NH];          // 2 MB
__device__ __half g_act[(size_t)NE * NT * NI];     // 33.5 MB

// ---------------- PTX helpers (base-PTX only: sm_100 safe) ----------------
__device__ __forceinline__ uint32_t smem_u32(const void* p) {
    uint32_t a;
    asm("{ .reg .u64 t; cvta.to.shared.u64 t, %1; cvt.u32.u64 %0, t; }" : "=r"(a) : "l"(p));
    return a;
}
__device__ __forceinline__ void ldm4(uint32_t* r, uint32_t addr) {
    asm volatile("ldmatrix.sync.aligned.m8n8.x4.shared.b16 {%0,%1,%2,%3}, [%4];"
                 : "=r"(r[0]), "=r"(r[1]), "=r"(r[2]), "=r"(r[3]) : "r"(addr));
}
__device__ __forceinline__ void mma16(float* c, const uint32_t* a, const uint32_t* b) {
    asm volatile(
        "mma.sync.aligned.m16n8k16.row.col.f32.f16.f16.f32 "
        "{%0,%1,%2,%3},{%4,%5,%6,%7},{%8,%9},{%0,%1,%2,%3};"
        : "+f"(c[0]), "+f"(c[1]), "+f"(c[2]), "+f"(c[3])
        : "r"(a[0]), "r"(a[1]), "r"(a[2]), "r"(a[3]), "r"(b[0]), "r"(b[1]));
}
__device__ __forceinline__ void cpa16(uint32_t dst, const void* src) {
    asm volatile("cp.async.cg.shared.global [%0], [%1], 16;" :: "r"(dst), "l"(src));
}
__device__ __forceinline__ void cp_commit() { asm volatile("cp.async.commit_group;"); }
template <int N> __device__ __forceinline__ void cp_wait() {
    asm volatile("cp.async.wait_group %0;" :: "n"(N));
}
__device__ __forceinline__ uint32_t pkh2(float a, float b) {
    __half2 t = __floats2half2_rn(a, b);
    return *reinterpret_cast<uint32_t*>(&t);
}

// smem tile geometry: 128 rows x 64 fp16 (=128B), padded row stride 144B
#define RSTRIDE 144
#define TILE_B  (128 * RSTRIDE)           // 18432
#define OFF_A(b) (1024 + (b) * 2 * TILE_B)
#define OFF_B(b) (1024 + (b) * 2 * TILE_B + TILE_B)
#define SMEM_TOT (1024 + 4 * TILE_B)      // 74752

// ---------------- kernel 0: zero out + counts, convert x -> fp16 ----------------
__global__ void prep_kernel(const float* __restrict__ x, float* __restrict__ out) {
    int i = blockIdx.x * 256 + threadIdx.x;
    if (i < NT * NH) { out[i] = 0.f; g_x16[i] = __float2half_rn(x[i]); }
    if (i < NE) g_counts[i] = 0;
}

// ---------------- kernel 1: router ----------------
__global__ void router_kernel(const float* __restrict__ logits) {
    int t = blockIdx.x * 256 + threadIdx.x;
    if (t >= NT) return;
    float b0 = -1e30f, b1 = -1e30f;
    int i0 = 0, i1 = 0;
#pragma unroll
    for (int ei = 0; ei < NE; ++ei) {
        float l = logits[t * NE + ei];
        if (l > b0) { b1 = b0; i1 = i0; b0 = l; i0 = ei; }
        else if (l > b1) { b1 = l; i1 = ei; }
    }
    float w0 = 1.f / (1.f + expf(b1 - b0));
    float w1 = 1.f - w0;
    int s0 = atomicAdd(&g_counts[i0], 1);
    g_tok[i0 * NT + s0] = t;  g_gate[i0 * NT + s0] = w0;
    int s1 = atomicAdd(&g_counts[i1], 1);
    g_tok[i1 * NT + s1] = t;  g_gate[i1 * NT + s1] = w1;
}

// ---------------- GEMM1: h = x @ w13^T + fused SwiGLU -> g_act (fp16) ----------------
// R4 pipeline; warps whose 32-row span is entirely padding skip LDSM+MMA.
__global__ __launch_bounds__(256, 2)
void gemm1_k(const float* __restrict__ w13, const float* __restrict__ b13) {
    const int e   = blockIdx.z;
    const int cnt = g_counts[e];
    const int m0  = blockIdx.y * 128;
    if (m0 >= cnt) return;
    const int n0i = blockIdx.x * 64;
    const int S   = 16;

    extern __shared__ char sm[];
    const uint32_t smb = smem_u32(sm);
    const int tid = threadIdx.x, wid = tid >> 5, lane = tid & 31;
    const int lr = lane >> 2, lc = lane & 3;
    const int wm = (wid & 3) * 32, wn = (wid >> 2) * 32;
    const int mrem = cnt - m0;                 // 1..128 live rows in this block
    const bool live = (wm < mrem);             // warp-uniform tail skip
    int* sTok = (int*)sm;

    if (tid < 128) { int s = m0 + tid; sTok[tid] = (s < cnt) ? g_tok[e * NT + s] : 0; }
    __syncthreads();

    float acc[2][8][4];
#pragma unroll
    for (int mt = 0; mt < 2; ++mt)
#pragma unroll
        for (int nt = 0; nt < 8; ++nt)
#pragma unroll
            for (int i = 0; i < 4; ++i) acc[mt][nt][i] = 0.f;

    const int ar = tid >> 3,  ac = tid & 7;
    const int br = tid >> 4,  bc = tid & 15;
    const uint32_t aoff = (uint32_t)((wm + (lane & 15)) * RSTRIDE + (lane >> 4) * 16);
    const uint32_t boff = (uint32_t)(((lane & 7) + ((lane >> 4) << 3)) * RSTRIDE
                                     + ((lane >> 3) & 1) * 16);

    const __half* arow0 = g_x16 + (size_t)sTok[ar] * NH;
    const __half* arow1 = g_x16 + (size_t)sTok[ar + 32] * NH;
    const __half* arow2 = g_x16 + (size_t)sTok[ar + 64] * NH;
    const __half* arow3 = g_x16 + (size_t)sTok[ar + 96] * NH;

    float4 b4[8];
    // prologue: A(0) cp.async; B(0) LDG->STS; B(1) LDG
    cpa16(smb + OFF_A(0) + (ar)      * RSTRIDE + ac * 16, arow0 + ac * 8);
    cpa16(smb + OFF_A(0) + (ar + 32) * RSTRIDE + ac * 16, arow1 + ac * 8);
    cpa16(smb + OFF_A(0) + (ar + 64) * RSTRIDE + ac * 16, arow2 + ac * 8);
    cpa16(smb + OFF_A(0) + (ar + 96) * RSTRIDE + ac * 16, arow3 + ac * 8);
    cp_commit();
#pragma unroll
    for (int i = 0; i < 8; ++i) {
        int r = br + i * 16;
        int grow = (r < 64) ? (n0i + r) : (2048 + n0i + r - 64);
        b4[i] = *(const float4*)(w13 + ((size_t)e * 4096 + grow) * NH + bc * 4);
    }
#pragma unroll
    for (int i = 0; i < 8; ++i) {
        int r = br + i * 16;
        uint2 p = make_uint2(pkh2(b4[i].x, b4[i].y), pkh2(b4[i].z, b4[i].w));
        *(uint2*)(sm + OFF_B(0) + r * RSTRIDE + bc * 8) = p;
    }
#pragma unroll
    for (int i = 0; i < 8; ++i) {
        int r = br + i * 16;
        int grow = (r < 64) ? (n0i + r) : (2048 + n0i + r - 64);
        b4[i] = *(const float4*)(w13 + ((size_t)e * 4096 + grow) * NH + 64 + bc * 4);
    }
    cp_wait<0>();
    __syncthreads();

#pragma unroll 1
    for (int s = 0; s < S; ++s) {
        const int cur = s & 1;
        const uint32_t stA = OFF_A(cur), stB = OFF_B(cur);
        // fill alt buffer (single-barrier pipeline, R4)
        if (s < 15) {
            const int k0n = (s + 1) * 64;
            const uint32_t dst = smb + OFF_A(cur ^ 1);
            cpa16(dst + (ar)      * RSTRIDE + ac * 16, arow0 + k0n + ac * 8);
            cpa16(dst + (ar + 32) * RSTRIDE + ac * 16, arow1 + k0n + ac * 8);
            cpa16(dst + (ar + 64) * RSTRIDE + ac * 16, arow2 + k0n + ac * 8);
            cpa16(dst + (ar + 96) * RSTRIDE + ac * 16, arow3 + k0n + ac * 8);
            cp_commit();
#pragma unroll
            for (int i = 0; i < 8; ++i) {
                int r = br + i * 16;
                uint2 p = make_uint2(pkh2(b4[i].x, b4[i].y), pkh2(b4[i].z, b4[i].w));
                *(uint2*)(sm + OFF_B(cur ^ 1) + r * RSTRIDE + bc * 8) = p;
            }
        }
        if (s < 14) {
            const int k0n2 = (s + 2) * 64;
#pragma unroll
            for (int i = 0; i < 8; ++i) {
                int r = br + i * 16;
                int grow = (r < 64) ? (n0i + r) : (2048 + n0i + r - 64);
                b4[i] = *(const float4*)(w13 + ((size_t)e * 4096 + grow) * NH + k0n2 + bc * 4);
            }
        }
        // compute current buffer — tail warps with no live rows skip entirely
        if (live) {
#pragma unroll
            for (int k16 = 0; k16 < 4; ++k16) {
                uint32_t a[2][4];
                uint32_t abase = smb + stA + aoff + k16 * 32;
                ldm4(a[0], abase);
                ldm4(a[1], abase + 16 * RSTRIDE);
#pragma unroll
                for (int ntp = 0; ntp < 4; ++ntp) {
                    int browoff = ((ntp >= 2) ? 64 : 0) + wn + ((ntp & 1) << 4);
                    uint32_t b[4];
                    ldm4(b, smb + stB + boff + browoff * RSTRIDE + k16 * 32);
                    mma16(acc[0][ntp * 2],     a[0], b);
                    mma16(acc[1][ntp * 2],     a[1], b);
                    mma16(acc[0][ntp * 2 + 1], a[0], b + 2);
                    mma16(acc[1][ntp * 2 + 1], a[1], b + 2);
                }
            }
        }
        if (s < 15) cp_wait<0>();
        __syncthreads();
    }

    // epilogue: SwiGLU in registers, stage act tile in smem, coalesced store
    const float* bg = b13 + (size_t)e * 4096 + n0i;
    const float* bl = b13 + (size_t)e * 4096 + 2048 + n0i;
    if (live) {
#pragma unroll
        for (int mt = 0; mt < 2; ++mt)
#pragma unroll
            for (int nt = 0; nt < 4; ++nt)
#pragma unroll
                for (int i = 0; i < 2; ++i) {
                    int row = wm + mt * 16 + lr + i * 8;
                    int col = wn + nt * 8 + lc * 2;
                    float g0 = acc[mt][nt][i * 2 + 0] + bg[col];
                    float g1 = acc[mt][nt][i * 2 + 1] + bg[col + 1];
                    float l0 = acc[mt][nt + 4][i * 2 + 0] + bl[col];
                    float l1 = acc[mt][nt + 4][i * 2 + 1] + bl[col + 1];
                    float a0 = g0 * (1.f / (1.f + __expf(-1.702f * g0))) * (l0 + 1.0f);
                    float a1 = g1 * (1.f / (1.f + __expf(-1.702f * g1))) * (l1 + 1.0f);
                    *(uint32_t*)(sm + 1024 + row * RSTRIDE + col * 2) = pkh2(a0, a1);
                }
    }
    __syncthreads();
#pragma unroll
    for (int i = 0; i < 4; ++i) {
        int idx = i * 256 + tid;
        int r = idx >> 3, c = idx & 7;
        int slot = m0 + r;
        if (slot < cnt) {
            uint4 v = *(uint4*)(sm + 1024 + r * RSTRIDE + c * 16);
            *(uint4*)(g_act + ((size_t)e * NT + slot) * NI + n0i + c * 8) = v;
        }
    }
}

// ---------------- GEMM2: y = act @ w2^T, gated atomic scatter ----------------
__global__ __launch_bounds__(256, 2)
void gemm2_k(const float* __restrict__ w2, const float* __restrict__ b2,
             float* __restrict__ out) {
    const int e   = blockIdx.z;
    const int cnt = g_counts[e];
    const int m0  = blockIdx.y * 128;
    if (m0 >= cnt) return;
    const int n0  = blockIdx.x * 128;
    const int S   = 32;

    extern __shared__ char sm[];
    const uint32_t smb = smem_u32(sm);
    const int tid = threadIdx.x, wid = tid >> 5, lane = tid & 31;
    const int lr = lane >> 2, lc = lane & 3;
    const int wm = (wid & 3) * 32, wn = (wid >> 2) * 64;
    const int mrem = cnt - m0;
    const bool live = (wm < mrem);
    int*   sTok = (int*)sm;
    float* sG   = (float*)(sm + 512);

    if (tid < 128) {
        int slot = m0 + tid;
        sTok[tid] = (slot < cnt) ? g_tok[e * NT + slot] : 0;
        sG[tid]   = (slot < cnt) ? g_gate[e * NT + slot] : 0.f;
    }
    __syncthreads();

    float acc[2][8][4];
#pragma unroll
    for (int mt = 0; mt < 2; ++mt)
#pragma unroll
        for (int nt = 0; nt < 8; ++nt)
#pragma unroll
            for (int i = 0; i < 4; ++i) acc[mt][nt][i] = 0.f;

    const int ar = tid >> 3,  ac = tid & 7;
    const int br = tid >> 4,  bc = tid & 15;
    const uint32_t aoff = (uint32_t)((wm + (lane & 15)) * RSTRIDE + (lane >> 4) * 16);
    const uint32_t boff = (uint32_t)(((lane & 7) + ((lane >> 4) << 3)) * RSTRIDE
                                     + ((lane >> 3) & 1) * 16);

    const __half* abase = g_act + ((size_t)e * NT + m0 + ar) * NI;

    float4 b4[8];
    // prologue
#pragma unroll
    for (int i = 0; i < 4; ++i) {
        int r = ar + i * 32;
        cpa16(smb + OFF_A(0) + r * RSTRIDE + ac * 16,
              abase + (size_t)i * 32 * NI + ac * 8);
    }
    cp_commit();
#pragma unroll
    for (int i = 0; i < 8; ++i) {
        int r = br + i * 16;
        b4[i] = *(const float4*)(w2 + ((size_t)e * NH + n0 + r) * NI + bc * 4);
    }
#pragma unroll
    for (int i = 0; i < 8; ++i) {
        int r = br + i * 16;
        uint2 p = make_uint2(pkh2(b4[i].x, b4[i].y), pkh2(b4[i].z, b4[i].w));
        *(uint2*)(sm + OFF_B(0) + r * RSTRIDE + bc * 8) = p;
    }
#pragma unroll
    for (int i = 0; i < 8; ++i) {
        int r = br + i * 16;
        b4[i] = *(const float4*)(w2 + ((size_t)e * NH + n0 + r) * NI + 64 + bc * 4);
    }
    cp_wait<0>();
    __syncthreads();

#pragma unroll 1
    for (int s = 0; s < S; ++s) {
        const int cur = s & 1;
        const uint32_t stA = OFF_A(cur), stB = OFF_B(cur);
        if (s < 31) {
            const int k0n = (s + 1) * 64;
            const uint32_t dst = smb + OFF_A(cur ^ 1);
#pragma unroll
            for (int i = 0; i < 4; ++i) {
                int r = ar + i * 32;
                cpa16(dst + r * RSTRIDE + ac * 16,
                      abase + (size_t)i * 32 * NI + k0n + ac * 8);
            }
            cp_commit();
#pragma unroll
            for (int i = 0; i < 8; ++i) {
                int r = br + i * 16;
                uint2 p = make_uint2(pkh2(b4[i].x, b4[i].y), pkh2(b4[i].z, b4[i].w));
                *(uint2*)(sm + OFF_B(cur ^ 1) + r * RSTRIDE + bc * 8) = p;
            }
        }
        if (s < 30) {
            const int k0n2 = (s + 2) * 64;
#pragma unroll
            for (int i = 0; i < 8; ++i) {
                int r = br + i * 16;
                b4[i] = *(const float4*)(w2 + ((size_t)e * NH + n0 + r) * NI + k0n2 + bc * 4);
            }
        }
        if (live) {
#pragma unroll
            for (int k16 = 0; k16 < 4; ++k16) {
                uint32_t a[2][4];
                uint32_t abase2 = smb + stA + aoff + k16 * 32;
                ldm4(a[0], abase2);
                ldm4(a[1], abase2 + 16 * RSTRIDE);
#pragma unroll
                for (int ntp = 0; ntp < 4; ++ntp) {
                    uint32_t b[4];
                    ldm4(b, smb + stB + boff + (wn + ntp * 16) * RSTRIDE + k16 * 32);
                    mma16(acc[0][ntp * 2],     a[0], b);
                    mma16(acc[1][ntp * 2],     a[1], b);
                    mma16(acc[0][ntp * 2 + 1], a[0], b + 2);
                    mma16(acc[1][ntp * 2 + 1], a[1], b + 2);
                }
            }
        }
        if (s < 31) cp_wait<0>();
        __syncthreads();
    }

    // epilogue: out[tok, n0+col] += gate * (acc + b2)
    const float* bb = b2 + (size_t)e * NH + n0;
    if (live) {
#pragma unroll
        for (int mt = 0; mt < 2; ++mt)
#pragma unroll
            for (int i = 0; i < 2; ++i) {
                int row = wm + mt * 16 + lr + i * 8;
                int slot = m0 + row;
                if (slot >= cnt) continue;
                int tok = sTok[row];
                float gate = sG[row];
                float* orow = out + (size_t)tok * NH + n0;
#pragma unroll
                for (int nt = 0; nt < 8; ++nt) {
                    int col = wn + nt * 8 + lc * 2;
                    atomicAdd(orow + col,     gate * (acc[mt][nt][i * 2 + 0] + bb[col]));
                    atomicAdd(orow + col + 1, gate * (acc[mt][nt][i * 2 + 1] + bb[col + 1]));
                }
            }
    }
}

// ---------------- host entry ----------------
extern "C" void kernel_launch(void* const* d_in, const int* in_sizes, int n_in,
                              void* d_out, int out_size) {
    const float* x      = (const float*)d_in[0];
    const float* logits = (const float*)d_in[1];
    const float* w13    = (const float*)d_in[2];
    const float* w2     = (const float*)d_in[3];
    const float* b13    = (const float*)d_in[4];
    const float* b2     = (const float*)d_in[5];
    float* out          = (float*)d_out;

    cudaFuncSetAttribute(gemm1_k, cudaFuncAttributeMaxDynamicSharedMemorySize, SMEM_TOT);
    cudaFuncSetAttribute(gemm2_k, cudaFuncAttributeMaxDynamicSharedMemorySize, SMEM_TOT);

    prep_kernel<<<(NT * NH + 255) / 256, 256>>>(x, out);
    router_kernel<<<(NT + 255) / 256, 256>>>(logits);
    gemm1_k<<<dim3(NI / 64, NT / 128, NE), 256, SMEM_TOT>>>(w13, b13);
    gemm2_k<<<dim3(NH / 128, NT / 128, NE), 256, SMEM_TOT>>>(w2, b2, out);
}

// round 12
// speedup vs baseline: 1.4366x; 1.0839x over previous
#include <cuda_runtime.h>
#include <cuda_fp16.h>
#include <cstdint>

#define NE 8
#define NH 1024
#define NI 2048
#define NT 1024

// ---------------- device scratch (no allocations allowed) ----------------
__device__ int    g_counts[NE];
__device__ int    g_tok[NE * NT];
__device__ float  g_gate[NE * NT];
__device__ __half g_x16[(size_t)NT * NH];          // 2 MB
__device__ __half g_act[(size_t)NE * NT * NI];     // 33.5 MB

// ---------------- PTX helpers (base-PTX only: sm_100 safe) ----------------
__device__ __forceinline__ uint32_t smem_u32(const void* p) {
    uint32_t a;
    asm("{ .reg .u64 t; cvta.to.shared.u64 t, %1; cvt.u32.u64 %0, t; }" : "=r"(a) : "l"(p));
    return a;
}
__device__ __forceinline__ void ldm4(uint32_t* r, uint32_t addr) {
    asm volatile("ldmatrix.sync.aligned.m8n8.x4.shared.b16 {%0,%1,%2,%3}, [%4];"
                 : "=r"(r[0]), "=r"(r[1]), "=r"(r[2]), "=r"(r[3]) : "r"(addr));
}
__device__ __forceinline__ void mma16(float* c, const uint32_t* a, const uint32_t* b) {
    asm volatile(
        "mma.sync.aligned.m16n8k16.row.col.f32.f16.f16.f32 "
        "{%0,%1,%2,%3},{%4,%5,%6,%7},{%8,%9},{%0,%1,%2,%3};"
        : "+f"(c[0]), "+f"(c[1]), "+f"(c[2]), "+f"(c[3])
        : "r"(a[0]), "r"(a[1]), "r"(a[2]), "r"(a[3]), "r"(b[0]), "r"(b[1]));
}
__device__ __forceinline__ void cpa16(uint32_t dst, const void* src) {
    asm volatile("cp.async.cg.shared.global [%0], [%1], 16;" :: "r"(dst), "l"(src));
}
__device__ __forceinline__ void cp_commit() { asm volatile("cp.async.commit_group;"); }
template <int N> __device__ __forceinline__ void cp_wait() {
    asm volatile("cp.async.wait_group %0;" :: "n"(N));
}
__device__ __forceinline__ uint32_t pkh2(float a, float b) {
    __half2 t = __floats2half2_rn(a, b);
    return *reinterpret_cast<uint32_t*>(&t);
}

// smem tile geometry: 128 rows x 64 fp16 (=128B), padded row stride 144B
#define RSTRIDE 144
#define TILE_B  (128 * RSTRIDE)           // 18432
#define OFF_A(b) (1024 + (b) * 2 * TILE_B)
#define OFF_B(b) (1024 + (b) * 2 * TILE_B + TILE_B)
#define SMEM_TOT (1024 + 4 * TILE_B)      // 74752

// ---------------- kernel 0: zero out + counts, convert x -> fp16 ----------------
__global__ void prep_kernel(const float* __restrict__ x, float* __restrict__ out) {
    int i = blockIdx.x * 256 + threadIdx.x;
    if (i < NT * NH) { out[i] = 0.f; g_x16[i] = __float2half_rn(x[i]); }
    if (i < NE) g_counts[i] = 0;
}

// ---------------- kernel 1: router ----------------
__global__ void router_kernel(const float* __restrict__ logits) {
    int t = blockIdx.x * 256 + threadIdx.x;
    if (t >= NT) return;
    float b0 = -1e30f, b1 = -1e30f;
    int i0 = 0, i1 = 0;
#pragma unroll
    for (int ei = 0; ei < NE; ++ei) {
        float l = logits[t * NE + ei];
        if (l > b0) { b1 = b0; i1 = i0; b0 = l; i0 = ei; }
        else if (l > b1) { b1 = l; i1 = ei; }
    }
    float w0 = 1.f / (1.f + expf(b1 - b0));
    float w1 = 1.f - w0;
    int s0 = atomicAdd(&g_counts[i0], 1);
    g_tok[i0 * NT + s0] = t;  g_gate[i0 * NT + s0] = w0;
    int s1 = atomicAdd(&g_counts[i1], 1);
    g_tok[i1 * NT + s1] = t;  g_gate[i1 * NT + s1] = w1;
}

// ---------------- GEMM1 (R10 verbatim): h = x @ w13^T + fused SwiGLU ----------------
__global__ __launch_bounds__(256, 2)
void gemm1_k(const float* __restrict__ w13, const float* __restrict__ b13) {
    const int e   = blockIdx.z;
    const int cnt = g_counts[e];
    const int m0  = blockIdx.y * 128;
    if (m0 >= cnt) return;
    const int n0i = blockIdx.x * 64;
    const int S   = 16;

    extern __shared__ char sm[];
    const uint32_t smb = smem_u32(sm);
    const int tid = threadIdx.x, wid = tid >> 5, lane = tid & 31;
    const int lr = lane >> 2, lc = lane & 3;
    const int wm = (wid & 3) * 32, wn = (wid >> 2) * 32;
    const int mrem = cnt - m0;
    const bool live = (wm < mrem);
    int* sTok = (int*)sm;

    if (tid < 128) { int s = m0 + tid; sTok[tid] = (s < cnt) ? g_tok[e * NT + s] : 0; }
    __syncthreads();

    float acc[2][8][4];
#pragma unroll
    for (int mt = 0; mt < 2; ++mt)
#pragma unroll
        for (int nt = 0; nt < 8; ++nt)
#pragma unroll
            for (int i = 0; i < 4; ++i) acc[mt][nt][i] = 0.f;

    const int ar = tid >> 3,  ac = tid & 7;
    const int br = tid >> 4,  bc = tid & 15;
    const uint32_t aoff = (uint32_t)((wm + (lane & 15)) * RSTRIDE + (lane >> 4) * 16);
    const uint32_t boff = (uint32_t)(((lane & 7) + ((lane >> 4) << 3)) * RSTRIDE
                                     + ((lane >> 3) & 1) * 16);

    const __half* arow0 = g_x16 + (size_t)sTok[ar] * NH;
    const __half* arow1 = g_x16 + (size_t)sTok[ar + 32] * NH;
    const __half* arow2 = g_x16 + (size_t)sTok[ar + 64] * NH;
    const __half* arow3 = g_x16 + (size_t)sTok[ar + 96] * NH;

    float4 b4[8];
    cpa16(smb + OFF_A(0) + (ar)      * RSTRIDE + ac * 16, arow0 + ac * 8);
    cpa16(smb + OFF_A(0) + (ar + 32) * RSTRIDE + ac * 16, arow1 + ac * 8);
    cpa16(smb + OFF_A(0) + (ar + 64) * RSTRIDE + ac * 16, arow2 + ac * 8);
    cpa16(smb + OFF_A(0) + (ar + 96) * RSTRIDE + ac * 16, arow3 + ac * 8);
    cp_commit();
#pragma unroll
    for (int i = 0; i < 8; ++i) {
        int r = br + i * 16;
        int grow = (r < 64) ? (n0i + r) : (2048 + n0i + r - 64);
        b4[i] = *(const float4*)(w13 + ((size_t)e * 4096 + grow) * NH + bc * 4);
    }
#pragma unroll
    for (int i = 0; i < 8; ++i) {
        int r = br + i * 16;
        uint2 p = make_uint2(pkh2(b4[i].x, b4[i].y), pkh2(b4[i].z, b4[i].w));
        *(uint2*)(sm + OFF_B(0) + r * RSTRIDE + bc * 8) = p;
    }
#pragma unroll
    for (int i = 0; i < 8; ++i) {
        int r = br + i * 16;
        int grow = (r < 64) ? (n0i + r) : (2048 + n0i + r - 64);
        b4[i] = *(const float4*)(w13 + ((size_t)e * 4096 + grow) * NH + 64 + bc * 4);
    }
    cp_wait<0>();
    __syncthreads();

#pragma unroll 1
    for (int s = 0; s < S; ++s) {
        const int cur = s & 1;
        const uint32_t stA = OFF_A(cur), stB = OFF_B(cur);
        if (s < 15) {
            const int k0n = (s + 1) * 64;
            const uint32_t dst = smb + OFF_A(cur ^ 1);
            cpa16(dst + (ar)      * RSTRIDE + ac * 16, arow0 + k0n + ac * 8);
            cpa16(dst + (ar + 32) * RSTRIDE + ac * 16, arow1 + k0n + ac * 8);
            cpa16(dst + (ar + 64) * RSTRIDE + ac * 16, arow2 + k0n + ac * 8);
            cpa16(dst + (ar + 96) * RSTRIDE + ac * 16, arow3 + k0n + ac * 8);
            cp_commit();
#pragma unroll
            for (int i = 0; i < 8; ++i) {
                int r = br + i * 16;
                uint2 p = make_uint2(pkh2(b4[i].x, b4[i].y), pkh2(b4[i].z, b4[i].w));
                *(uint2*)(sm + OFF_B(cur ^ 1) + r * RSTRIDE + bc * 8) = p;
            }
        }
        if (s < 14) {
            const int k0n2 = (s + 2) * 64;
#pragma unroll
            for (int i = 0; i < 8; ++i) {
                int r = br + i * 16;
                int grow = (r < 64) ? (n0i + r) : (2048 + n0i + r - 64);
                b4[i] = *(const float4*)(w13 + ((size_t)e * 4096 + grow) * NH + k0n2 + bc * 4);
            }
        }
        if (live) {
#pragma unroll
            for (int k16 = 0; k16 < 4; ++k16) {
                uint32_t a[2][4];
                uint32_t abase = smb + stA + aoff + k16 * 32;
                ldm4(a[0], abase);
                ldm4(a[1], abase + 16 * RSTRIDE);
#pragma unroll
                for (int ntp = 0; ntp < 4; ++ntp) {
                    int browoff = ((ntp >= 2) ? 64 : 0) + wn + ((ntp & 1) << 4);
                    uint32_t b[4];
                    ldm4(b, smb + stB + boff + browoff * RSTRIDE + k16 * 32);
                    mma16(acc[0][ntp * 2],     a[0], b);
                    mma16(acc[1][ntp * 2],     a[1], b);
                    mma16(acc[0][ntp * 2 + 1], a[0], b + 2);
                    mma16(acc[1][ntp * 2 + 1], a[1], b + 2);
                }
            }
        }
        if (s < 15) cp_wait<0>();
        __syncthreads();
    }

    const float* bg = b13 + (size_t)e * 4096 + n0i;
    const float* bl = b13 + (size_t)e * 4096 + 2048 + n0i;
    if (live) {
#pragma unroll
        for (int mt = 0; mt < 2; ++mt)
#pragma unroll
            for (int nt = 0; nt < 4; ++nt)
#pragma unroll
                for (int i = 0; i < 2; ++i) {
                    int row = wm + mt * 16 + lr + i * 8;
                    int col = wn + nt * 8 + lc * 2;
                    float g0 = acc[mt][nt][i * 2 + 0] + bg[col];
                    float g1 = acc[mt][nt][i * 2 + 1] + bg[col + 1];
                    float l0 = acc[mt][nt + 4][i * 2 + 0] + bl[col];
                    float l1 = acc[mt][nt + 4][i * 2 + 1] + bl[col + 1];
                    float a0 = g0 * (1.f / (1.f + __expf(-1.702f * g0))) * (l0 + 1.0f);
                    float a1 = g1 * (1.f / (1.f + __expf(-1.702f * g1))) * (l1 + 1.0f);
                    *(uint32_t*)(sm + 1024 + row * RSTRIDE + col * 2) = pkh2(a0, a1);
                }
    }
    __syncthreads();
#pragma unroll
    for (int i = 0; i < 4; ++i) {
        int idx = i * 256 + tid;
        int r = idx >> 3, c = idx & 7;
        int slot = m0 + r;
        if (slot < cnt) {
            uint4 v = *(uint4*)(sm + 1024 + r * RSTRIDE + c * 16);
            *(uint4*)(g_act + ((size_t)e * NT + slot) * NI + n0i + c * 8) = v;
        }
    }
}

// ---------------- GEMM2 (K-split x2): y = act @ w2^T, gated atomic scatter ----------------
// grid.x encodes (n-block, k-half): n0 = (bx>>1)*128, kh = bx&1, K range = kh*1024..+1024.
// Doubles live CTAs (~154 -> ~308 = 2/SM) at unchanged CTA size -> 16 warps/SM.
__global__ __launch_bounds__(256, 2)
void gemm2_k(const float* __restrict__ w2, const float* __restrict__ b2,
             float* __restrict__ out) {
    const int e   = blockIdx.z;
    const int cnt = g_counts[e];
    const int m0  = blockIdx.y * 128;
    if (m0 >= cnt) return;
    const int bx  = blockIdx.x;
    const int n0  = (bx >> 1) * 128;
    const int kh  = bx & 1;
    const int kb  = kh * 1024;          // K base for this half
    const int S   = 16;                 // 16 stages of BK=64 -> K=1024

    extern __shared__ char sm[];
    const uint32_t smb = smem_u32(sm);
    const int tid = threadIdx.x, wid = tid >> 5, lane = tid & 31;
    const int lr = lane >> 2, lc = lane & 3;
    const int wm = (wid & 3) * 32, wn = (wid >> 2) * 64;
    const int mrem = cnt - m0;
    const bool live = (wm < mrem);
    int*   sTok = (int*)sm;
    float* sG   = (float*)(sm + 512);

    if (tid < 128) {
        int slot = m0 + tid;
        sTok[tid] = (slot < cnt) ? g_tok[e * NT + slot] : 0;
        sG[tid]   = (slot < cnt) ? g_gate[e * NT + slot] : 0.f;
    }
    __syncthreads();

    float acc[2][8][4];
#pragma unroll
    for (int mt = 0; mt < 2; ++mt)
#pragma unroll
        for (int nt = 0; nt < 8; ++nt)
#pragma unroll
            for (int i = 0; i < 4; ++i) acc[mt][nt][i] = 0.f;

    const int ar = tid >> 3,  ac = tid & 7;
    const int br = tid >> 4,  bc = tid & 15;
    const uint32_t aoff = (uint32_t)((wm + (lane & 15)) * RSTRIDE + (lane >> 4) * 16);
    const uint32_t boff = (uint32_t)(((lane & 7) + ((lane >> 4) << 3)) * RSTRIDE
                                     + ((lane >> 3) & 1) * 16);

    const __half* abase = g_act + ((size_t)e * NT + m0 + ar) * NI + kb;

    float4 b4[8];
    // prologue: A(0) cp.async; B(0) LDG->STS; B(1) LDG
#pragma unroll
    for (int i = 0; i < 4; ++i) {
        int r = ar + i * 32;
        cpa16(smb + OFF_A(0) + r * RSTRIDE + ac * 16,
              abase + (size_t)i * 32 * NI + ac * 8);
    }
    cp_commit();
#pragma unroll
    for (int i = 0; i < 8; ++i) {
        int r = br + i * 16;
        b4[i] = *(const float4*)(w2 + ((size_t)e * NH + n0 + r) * NI + kb + bc * 4);
    }
#pragma unroll
    for (int i = 0; i < 8; ++i) {
        int r = br + i * 16;
        uint2 p = make_uint2(pkh2(b4[i].x, b4[i].y), pkh2(b4[i].z, b4[i].w));
        *(uint2*)(sm + OFF_B(0) + r * RSTRIDE + bc * 8) = p;
    }
#pragma unroll
    for (int i = 0; i < 8; ++i) {
        int r = br + i * 16;
        b4[i] = *(const float4*)(w2 + ((size_t)e * NH + n0 + r) * NI + kb + 64 + bc * 4);
    }
    cp_wait<0>();
    __syncthreads();

#pragma unroll 1
    for (int s = 0; s < S; ++s) {
        const int cur = s & 1;
        const uint32_t stA = OFF_A(cur), stB = OFF_B(cur);
        if (s < S - 1) {
            const int koff = (s + 1) * 64;
            const uint32_t dst = smb + OFF_A(cur ^ 1);
#pragma unroll
            for (int i = 0; i < 4; ++i) {
                int r = ar + i * 32;
                cpa16(dst + r * RSTRIDE + ac * 16,
                      abase + (size_t)i * 32 * NI + koff + ac * 8);
            }
            cp_commit();
#pragma unroll
            for (int i = 0; i < 8; ++i) {
                int r = br + i * 16;
                uint2 p = make_uint2(pkh2(b4[i].x, b4[i].y), pkh2(b4[i].z, b4[i].w));
                *(uint2*)(sm + OFF_B(cur ^ 1) + r * RSTRIDE + bc * 8) = p;
            }
        }
        if (s < S - 2) {
            const int koff2 = kb + (s + 2) * 64;
#pragma unroll
            for (int i = 0; i < 8; ++i) {
                int r = br + i * 16;
                b4[i] = *(const float4*)(w2 + ((size_t)e * NH + n0 + r) * NI + koff2 + bc * 4);
            }
        }
        if (live) {
#pragma unroll
            for (int k16 = 0; k16 < 4; ++k16) {
                uint32_t a[2][4];
                uint32_t abase2 = smb + stA + aoff + k16 * 32;
                ldm4(a[0], abase2);
                ldm4(a[1], abase2 + 16 * RSTRIDE);
#pragma unroll
                for (int ntp = 0; ntp < 4; ++ntp) {
                    uint32_t b[4];
                    ldm4(b, smb + stB + boff + (wn + ntp * 16) * RSTRIDE + k16 * 32);
                    mma16(acc[0][ntp * 2],     a[0], b);
                    mma16(acc[1][ntp * 2],     a[1], b);
                    mma16(acc[0][ntp * 2 + 1], a[0], b + 2);
                    mma16(acc[1][ntp * 2 + 1], a[1], b + 2);
                }
            }
        }
        if (s < S - 1) cp_wait<0>();
        __syncthreads();
    }

    // epilogue: out[tok, n0+col] += gate * (partial + (kh==0 ? b2 : 0))
    const float* bb = b2 + (size_t)e * NH + n0;
    if (live) {
#pragma unroll
        for (int mt = 0; mt < 2; ++mt)
#pragma unroll
            for (int i = 0; i < 2; ++i) {
                int row = wm + mt * 16 + lr + i * 8;
                int slot = m0 + row;
                if (slot >= cnt) continue;
                int tok = sTok[row];
                float gate = sG[row];
                float* orow = out + (size_t)tok * NH + n0;
#pragma unroll
                for (int nt = 0; nt < 8; ++nt) {
                    int col = wn + nt * 8 + lc * 2;
                    float bias0 = kh ? 0.f : bb[col];
                    float bias1 = kh ? 0.f : bb[col + 1];
                    atomicAdd(orow + col,     gate * (acc[mt][nt][i * 2 + 0] + bias0));
                    atomicAdd(orow + col + 1, gate * (acc[mt][nt][i * 2 + 1] + bias1));
                }
            }
    }
}

// ---------------- host entry ----------------
extern "C" void kernel_launch(void* const* d_in, const int* in_sizes, int n_in,
                              void* d_out, int out_size) {
    const float* x      = (const float*)d_in[0];
    const float* logits = (const float*)d_in[1];
    const float* w13    = (const float*)d_in[2];
    const float* w2     = (const float*)d_in[3];
    const float* b13    = (const float*)d_in[4];
    const float* b2     = (const float*)d_in[5];
    float* out          = (float*)d_out;

    cudaFuncSetAttribute(gemm1_k, cudaFuncAttributeMaxDynamicSharedMemorySize, SMEM_TOT);
    cudaFuncSetAttribute(gemm2_k, cudaFuncAttributeMaxDynamicSharedMemorySize, SMEM_TOT);

    prep_kernel<<<(NT * NH + 255) / 256, 256>>>(x, out);
    router_kernel<<<(NT + 255) / 256, 256>>>(logits);
    gemm1_k<<<dim3(NI / 64, NT / 128, NE), 256, SMEM_TOT>>>(w13, b13);
    gemm2_k<<<dim3((NH / 128) * 2, NT / 128, NE), 256, SMEM_TOT>>>(w2, b2, out);
}